// round 16
// baseline (speedup 1.0000x reference)
#include <cuda_runtime.h>
#include <math.h>
#include <stdint.h>

#define Dd 64
#define DM 128
#define DI 256
#define Bq 128
#define NN 200
#define FEW 5
#define NRELS 500
#define NPQ (Bq*NN)
#define NPS (FEW*NN)
#define NPTOT (2*NPQ + 2*NPS)   // 53200
#define CAP 512
#define LN_EPS 0.001f
#define GRID1 296               // fused scatter+rescal: 2 blocks/SM
#define GRID2 148
#define NT 512
#define SCHUNK1 180             // 296*180 >= 53200
#define NROWS (Bq + FEW)        // 133
#define SUMSZ (NROWS * 128)

// k2 stage-A smem layout
#define AMS   0
#define AX    128
#define APART 256
#define ASA   768
#define ASH   1024
#define ASR   1152
#define ASC   1216

// k2 stage-B/C smem layout — packed 512-col gates
#define SXP   0
#define SP1   2048
#define SP2   4096
#define SP3   6144
#define SHT   8192
#define SQ    8704
#define SSUP  9216
#define SLOG  9856
#define SATT  9888
#define SRED  9920
#define SMEMF 10240

// ---------------- device scratch ----------------
__device__ int   g_cnt[512];                 // zero-init; self-zeroed by rescal pops
__device__ int2  g_pairs[NRELS*CAP + 8];
__device__ float g_sum[SUMSZ];               // natural layout [row][col]
__device__ float g_query_g[Bq*DM];
__device__ float g_support_g[FEW*DM];
__device__ float g_SW[FEW*512];
__device__ int   g_relctr;
__device__ unsigned long long g_bar1;        // k1 barrier counter, monotonic
__device__ unsigned long long g_bar2;        // k2 barrier counter, monotonic

__device__ __forceinline__ float sigmoidf_(float x) { return 1.0f / (1.0f + expf(-x)); }

#define FPACK2(d, f)      asm("mov.b64 %0, {%1, %1};" : "=l"(d) : "f"(f))
#define FMA2(acc, e, r)   asm("fma.rn.f32x2 %0, %1, %2, %3;" : "=l"(acc) : "l"(e), "l"(r), "l"(acc))
#define UNPACK2(lo, hi, v) asm("mov.b64 {%0, %1}, %2;" : "=f"(lo), "=f"(hi) : "l"(v))

__device__ __forceinline__ unsigned long long ctr_read(unsigned long long* p) {
    unsigned long long v;
    asm volatile("ld.global.acquire.gpu.u64 %0, [%1];" : "=l"(v) : "l"(p) : "memory");
    return v;
}
__device__ __forceinline__ void grid_bar_on(unsigned long long* p, unsigned long long base,
                                            int k, int n) {
    __syncthreads();
    if (threadIdx.x == 0) {
        __threadfence();
        atomicAdd(p, 1ULL);
        unsigned long long target = base + (unsigned long long)n * (unsigned long long)(k + 1);
        while (ctr_read(p) < target) {}
        __threadfence();
    }
    __syncthreads();
}

__device__ __forceinline__ int dest_base(int idx) {
    if (idx < 2*NPQ) {
        int half = (idx >= NPQ);
        int b = (idx - half * NPQ) / NN;
        return b * 128 + half * 64;
    } else {
        int i2 = idx - 2*NPQ;
        int half = (i2 >= NPS);
        int s = (i2 - half * NPS) / NN;
        return (Bq + s) * 128 + half * 64;
    }
}

// ================= KERNEL 1: fused scatter + binned RESCAL =================
__global__ __launch_bounds__(NT, 2) void k1_scatter_rescal(
        const int2* __restrict__ ql, const int2* __restrict__ qr,
        const int2* __restrict__ sl, const int2* __restrict__ sr,
        const float* __restrict__ ent_emb, const float* __restrict__ rel_mat) {
    __shared__ __align__(16) float sR[4352];        // pitch-68 R tile
    __shared__ __align__(16) float sE01[16][128];
    __shared__ __align__(16) float sE23[16][128];
    __shared__ int s_r;
    __shared__ int s_c;
    __shared__ unsigned long long s_base;
    int t = threadIdx.x, bid = blockIdx.x;
    if (t == 0) s_base = (ctr_read(&g_bar1) / GRID1) * GRID1;
    __syncthreads();
    unsigned long long bbase = s_base;

    // ---- scatter phase (296 blocks): reset queue, zero g_sum, bin pairs ----
    if (bid == 0 && t == 0) g_relctr = 0;
    for (int i = bid * NT + t; i < SUMSZ; i += GRID1 * NT) g_sum[i] = 0.0f;
    {
        int lo = bid * SCHUNK1, hi = min(lo + SCHUNK1, NPTOT);
        for (int idx = lo + t; idx < hi; idx += NT) {
            int2 c;
            if (idx < NPQ)                 c = ql[idx];
            else if (idx < 2*NPQ)          c = qr[idx - NPQ];
            else if (idx < 2*NPQ + NPS)    c = sl[idx - 2*NPQ];
            else                           c = sr[idx - 2*NPQ - NPS];
            int pos = atomicAdd(&g_cnt[c.x], 1);
            if (pos < CAP) g_pairs[c.x * CAP + pos] = make_int2(idx, c.y);
        }
    }
    grid_bar_on(&g_bar1, bbase, 0, GRID1);

    // ---- rescal phase: dynamic rel queue, warp-autonomous groups ----
    int w = t >> 5, lane = t & 31;
    float* e01 = &sE01[w][0];
    float* e23 = &sE23[w][0];
    for (;;) {
        if (t == 0) {
            int r = atomicAdd(&g_relctr, 1);
            s_r = r;
            if (r < NRELS) { s_c = g_cnt[r]; g_cnt[r] = 0; }
        }
        __syncthreads();
        int r = s_r;
        if (r >= NRELS) break;
        int cnt = s_c;
        if (cnt > 0) {
            if (cnt > CAP) cnt = CAP;
            const float* R = rel_mat + (size_t)r * 4096;
            for (int i = t; i < 4096; i += NT) sR[(i >> 6) * 68 + (i & 63)] = R[i];
            __syncthreads();
            for (int base = w * 4; base < cnt; base += 64) {
                int np = min(4, cnt - base);
                int2 pr[4];
                float2 ev[4];
                #pragma unroll
                for (int p = 0; p < 4; p++) pr[p] = g_pairs[r * CAP + base + p];
                #pragma unroll
                for (int p = 0; p < 4; p++)
                    ev[p] = ((const float2*)(ent_emb + (size_t)pr[p].y * 64))[lane];
                #pragma unroll
                for (int p = 0; p < 4; p++) {
                    float* dstE = (p < 2) ? e01 : e23;
                    int pp = p & 1;
                    dstE[4*lane + pp]     = ev[p].x;
                    dstE[4*lane + 2 + pp] = ev[p].y;
                }
                __syncwarp();
                unsigned long long aA01=0, aA23=0, aB01=0, aB23=0;
                #pragma unroll
                for (int j4 = 0; j4 < 64; j4 += 4) {
                    float4 rA = *(const float4*)&sR[lane * 68 + j4];
                    float4 rB = *(const float4*)&sR[(lane + 32) * 68 + j4];
                    ulonglong2 E01a = *(const ulonglong2*)(e01 + j4*2);
                    ulonglong2 E01b = *(const ulonglong2*)(e01 + j4*2 + 4);
                    ulonglong2 E23a = *(const ulonglong2*)(e23 + j4*2);
                    ulonglong2 E23b = *(const ulonglong2*)(e23 + j4*2 + 4);
                    unsigned long long dA, dB;
                    FPACK2(dA, rA.x); FPACK2(dB, rB.x);
                    FMA2(aA01, E01a.x, dA); FMA2(aA23, E23a.x, dA);
                    FMA2(aB01, E01a.x, dB); FMA2(aB23, E23a.x, dB);
                    FPACK2(dA, rA.y); FPACK2(dB, rB.y);
                    FMA2(aA01, E01a.y, dA); FMA2(aA23, E23a.y, dA);
                    FMA2(aB01, E01a.y, dB); FMA2(aB23, E23a.y, dB);
                    FPACK2(dA, rA.z); FPACK2(dB, rB.z);
                    FMA2(aA01, E01b.x, dA); FMA2(aA23, E23b.x, dA);
                    FMA2(aB01, E01b.x, dB); FMA2(aB23, E23b.x, dB);
                    FPACK2(dA, rA.w); FPACK2(dB, rB.w);
                    FMA2(aA01, E01b.y, dA); FMA2(aA23, E23b.y, dA);
                    FMA2(aB01, E01b.y, dB); FMA2(aB23, E23b.y, dB);
                }
                float accA[4], accB[4];
                UNPACK2(accA[0], accA[1], aA01); UNPACK2(accA[2], accA[3], aA23);
                UNPACK2(accB[0], accB[1], aB01); UNPACK2(accB[2], accB[3], aB23);
                #pragma unroll
                for (int p = 0; p < 4; p++) {
                    if (p < np) {
                        int db = dest_base(pr[p].x);
                        asm volatile("red.global.add.f32 [%0], %1;"
                            :: "l"(&g_sum[db + lane]), "f"(accA[p]) : "memory");
                        asm volatile("red.global.add.f32 [%0], %1;"
                            :: "l"(&g_sum[db + lane + 32]), "f"(accB[p]) : "memory");
                    }
                }
                __syncwarp();
            }
        }
        __syncthreads();   // protect sR / s_r / s_c reuse
    }
}

// ---------------- packed 4-row GEMM: (4x128) @ (128 x packed512), 4-way K-split ----------------
template<bool XPROJ>
__device__ __forceinline__ void gemm4p(float* sm, const float* __restrict__ Bmat,
        const float* __restrict__ bih, const float* __restrict__ bhh, int t) {
    int kh = t >> 7, u = t & 127;
    int c4p = u * 4;
    int gate = c4p >> 7;
    int colo = gate * 256 + (c4p & 127);
    const float* Bp = Bmat + (size_t)(kh * 32) * 1024 + colo;
    const float* Ap = sm + SHT + kh * 32 * 4;
    unsigned long long acc[8];
    #pragma unroll
    for (int i = 0; i < 8; i++) acc[i] = 0ULL;
    #pragma unroll 8
    for (int k = 0; k < 32; k++) {
        float4 a4 = *(const float4*)(Ap + k * 4);
        ulonglong2 bv = *(const ulonglong2*)(Bp + (size_t)k * 1024);
        unsigned long long ar;
        FPACK2(ar, a4.x); FMA2(acc[0], bv.x, ar); FMA2(acc[1], bv.y, ar);
        FPACK2(ar, a4.y); FMA2(acc[2], bv.x, ar); FMA2(acc[3], bv.y, ar);
        FPACK2(ar, a4.z); FMA2(acc[4], bv.x, ar); FMA2(acc[5], bv.y, ar);
        FPACK2(ar, a4.w); FMA2(acc[6], bv.x, ar); FMA2(acc[7], bv.y, ar);
    }
    if (kh) {
        float* pdst = sm + SP1 + (kh - 1) * 2048;
        #pragma unroll
        for (int r = 0; r < 4; r++) {
            float o0, o1, o2, o3;
            UNPACK2(o0, o1, acc[r*2]); UNPACK2(o2, o3, acc[r*2+1]);
            *(float4*)&pdst[r * 512 + c4p] = make_float4(o0, o1, o2, o3);
        }
    }
    __syncthreads();
    if (kh == 0) {
        float4 sw[FEW];
        float4 bb;
        if (XPROJ) {
            bb = make_float4(bih[colo]+bhh[colo], bih[colo+1]+bhh[colo+1],
                             bih[colo+2]+bhh[colo+2], bih[colo+3]+bhh[colo+3]);
        } else {
            #pragma unroll
            for (int j = 0; j < FEW; j++) sw[j] = *(const float4*)&g_SW[j * 512 + c4p];
        }
        #pragma unroll
        for (int r = 0; r < 4; r++) {
            float o0, o1, o2, o3;
            UNPACK2(o0, o1, acc[r*2]); UNPACK2(o2, o3, acc[r*2+1]);
            float4 p1 = *(const float4*)&sm[SP1 + r * 512 + c4p];
            float4 p2 = *(const float4*)&sm[SP2 + r * 512 + c4p];
            float4 p3 = *(const float4*)&sm[SP3 + r * 512 + c4p];
            o0 += p1.x + p2.x + p3.x; o1 += p1.y + p2.y + p3.y;
            o2 += p1.z + p2.z + p3.z; o3 += p1.w + p2.w + p3.w;
            if (XPROJ) {
                o0 += bb.x; o1 += bb.y; o2 += bb.z; o3 += bb.w;
                *(float4*)&sm[SXP + r * 512 + c4p] = make_float4(o0, o1, o2, o3);
            } else {
                float4 xv = *(const float4*)&sm[SXP + r * 512 + c4p];
                o0 += xv.x; o1 += xv.y; o2 += xv.z; o3 += xv.w;
                #pragma unroll
                for (int j = 0; j < FEW; j++) {
                    float aj = sm[SATT + r * 8 + j];
                    o0 += aj * sw[j].x; o1 += aj * sw[j].y;
                    o2 += aj * sw[j].z; o3 += aj * sw[j].w;
                }
                *(float4*)&sm[SP1 + r * 512 + c4p] = make_float4(o0, o1, o2, o3);
            }
        }
    }
    __syncthreads();
}

// ---------------- LSTM elementwise + attention, 2-sync version ----------------
__device__ __forceinline__ void elt4p(float* sm, const float* __restrict__ gp_base,
                                      float& c, int t, int row0, int last, float* __restrict__ out) {
    int r = t >> 7, u = t & 127;
    const float* gp = gp_base + r * 512;
    float gi = gp[u], gf = gp[128 + u], gg = gp[256 + u], go = gp[384 + u];
    c = sigmoidf_(gf) * c + sigmoidf_(gi) * tanhf(gg);
    float h = sm[SQ + r * 128 + u] + sigmoidf_(go) * tanhf(c);
    sm[SHT + u * 4 + r] = h;
    int lane = t & 31, wid = t >> 5;
    float p[FEW];
    #pragma unroll
    for (int j = 0; j < FEW; j++) p[j] = h * sm[SSUP + j * 128 + u];
    #pragma unroll
    for (int j = 0; j < FEW; j++)
        for (int o = 16; o; o >>= 1) p[j] += __shfl_down_sync(0xffffffff, p[j], o);
    if (lane == 0) {
        #pragma unroll
        for (int j = 0; j < FEW; j++) sm[SRED + wid * 5 + j] = p[j];
    }
    __syncthreads();
    if (t < 32) {
        int rr = t >> 3, j = t & 7;
        if (j < FEW) {
            int w0 = rr * 4;
            sm[SLOG + rr * 8 + j] = sm[SRED + w0*5 + j] + sm[SRED + (w0+1)*5 + j]
                                  + sm[SRED + (w0+2)*5 + j] + sm[SRED + (w0+3)*5 + j];
        }
    }
    __syncthreads();
    if (last) {
        if (t < 4) {
            #pragma unroll
            for (int j = 0; j < FEW; j++) out[(row0 + t) * FEW + j] = sm[SLOG + t * 8 + j];
        }
        return;
    }
    if (t < 4) {
        float mx = sm[SLOG + t * 8];
        #pragma unroll
        for (int j = 1; j < FEW; j++) mx = fmaxf(mx, sm[SLOG + t * 8 + j]);
        float s = 0.0f, e[FEW];
        #pragma unroll
        for (int j = 0; j < FEW; j++) { e[j] = expf(sm[SLOG + t * 8 + j] - mx); s += e[j]; }
        #pragma unroll
        for (int j = 0; j < FEW; j++) sm[SATT + t * 8 + j] = e[j] / s;
    }
    __syncthreads();
}

// ================= KERNEL 2: gcn+supp + LSTM tail =================
__global__ __launch_bounds__(NT, 1) void k2_tail(
        const float* __restrict__ qld, const float* __restrict__ qrd,
        const float* __restrict__ sld, const float* __restrict__ srd,
        const float* __restrict__ gcn_w, const float* __restrict__ gcn_wb, const float* __restrict__ gcn_b,
        const float* __restrict__ w1, const float* __restrict__ b1,
        const float* __restrict__ w2, const float* __restrict__ b2,
        const float* __restrict__ lg, const float* __restrict__ lb,
        const float* __restrict__ wih, const float* __restrict__ whh,
        const float* __restrict__ bih, const float* __restrict__ bhh,
        float* __restrict__ out) {
    __shared__ __align__(16) float smem[SMEMF];
    __shared__ unsigned long long s_base;
    int t = threadIdx.x, bid = blockIdx.x;
    if (t == 0) s_base = (ctr_read(&g_bar2) / (2ULL * GRID2)) * (2ULL * GRID2);
    __syncthreads();
    unsigned long long bbase = s_base;

    if (bid < NROWS) {
        if (t < 128) smem[AMS + t] = g_sum[bid * 128 + t];
        __syncthreads();
        {
            int o = t & 127, ks = t >> 7;
            int hh = o >> 6, col = o & 63;
            float acc = 0.0f;
            #pragma unroll
            for (int i = 0; i < 16; i++) {
                int k = ks * 16 + i;
                acc += smem[AMS + hh * 64 + k] * gcn_w[k * 64 + col];
            }
            smem[APART + ks * 128 + o] = acc;
        }
        __syncthreads();
        float degL = (bid < Bq) ? qld[bid] : sld[bid - Bq];
        float degR = (bid < Bq) ? qrd[bid] : srd[bid - Bq];
        if (t < 128) {
            float acc = smem[APART + t] + smem[APART + 128 + t]
                      + smem[APART + 256 + t] + smem[APART + 384 + t];
            acc += (float)NN * (gcn_wb[t & 63] + gcn_b[t & 63]);
            smem[AX + t] = tanhf(acc / ((t >> 6) ? degR : degL));
        }
        __syncthreads();
        {   // GEMV1: 2-way k-split, 4 accumulators to break FADD chain
            int half = t >> 8, o = t & 255;
            float a0 = 0.f, a1 = 0.f, a2 = 0.f, a3 = 0.f;
            const float* xk = smem + AX + half * 64;
            const float* wk = w1 + (size_t)(half * 64) * DI + o;
            #pragma unroll
            for (int i = 0; i < 64; i += 4) {
                a0 += xk[i]   * wk[(size_t)i * DI];
                a1 += xk[i+1] * wk[(size_t)(i+1) * DI];
                a2 += xk[i+2] * wk[(size_t)(i+2) * DI];
                a3 += xk[i+3] * wk[(size_t)(i+3) * DI];
            }
            smem[APART + half * 256 + o] = (a0 + a1) + (a2 + a3);
        }
        __syncthreads();
        if (t < DI) smem[ASA + t] = fmaxf(smem[APART + t] + smem[APART + 256 + t] + b1[t], 0.0f);
        __syncthreads();
        {   // GEMV2: 4-way k-split, 4 accumulators
            int ks = t >> 7, o = t & 127;
            float a0 = 0.f, a1 = 0.f, a2 = 0.f, a3 = 0.f;
            const float* xk = smem + ASA + ks * 64;
            const float* wk = w2 + (size_t)(ks * 64) * DM + o;
            #pragma unroll
            for (int i = 0; i < 64; i += 4) {
                a0 += xk[i]   * wk[(size_t)i * DM];
                a1 += xk[i+1] * wk[(size_t)(i+1) * DM];
                a2 += xk[i+2] * wk[(size_t)(i+2) * DM];
                a3 += xk[i+3] * wk[(size_t)(i+3) * DM];
            }
            smem[APART + ks * 128 + o] = (a0 + a1) + (a2 + a3);
        }
        __syncthreads();
        if (t < DM) {
            smem[ASH + t] = smem[APART + t] + smem[APART + 128 + t] + smem[APART + 256 + t]
                          + smem[APART + 384 + t] + b2[t] + smem[AX + t];
        }
        __syncthreads();
        if (t < 64) smem[ASR + t] = smem[ASH + t] + smem[ASH + t + 64];
        __syncthreads();
        if (t < 32) {
            float v = smem[ASR + t] + smem[ASR + t + 32];
            for (int o = 16; o; o >>= 1) v += __shfl_down_sync(0xffffffff, v, o);
            if (t == 0) smem[ASC] = v / (float)DM;
        }
        __syncthreads();
        float mu = smem[ASC];
        if (t < 64) {
            float d0 = smem[ASH + t] - mu, d1 = smem[ASH + t + 64] - mu;
            smem[ASR + t] = d0 * d0 + d1 * d1;
        }
        __syncthreads();
        if (t < 32) {
            float v = smem[ASR + t] + smem[ASR + t + 32];
            for (int o = 16; o; o >>= 1) v += __shfl_down_sync(0xffffffff, v, o);
            if (t == 0) smem[ASC + 1] = sqrtf(v / (float)(DM - 1));
        }
        __syncthreads();
        if (t < DM) {
            float* y = (bid < Bq) ? (g_query_g + bid * DM) : (g_support_g + (bid - Bq) * DM);
            y[t] = (smem[ASH + t] - mu) / (smem[ASC + 1] + LN_EPS) * lg[t] + lb[t];
        }
    }
    grid_bar_on(&g_bar2, bbase, 0, GRID2);

    int row0 = bid * 4;
    float cst = 0.0f;
    if (bid < 32) {
        {
            int r = t >> 7, k = t & 127;
            float v = g_query_g[(size_t)(row0 + r) * 128 + k];
            smem[SHT + k * 4 + r] = v;
            smem[SQ + r * 128 + k] = v;
            for (int i = t; i < FEW * 128; i += NT) smem[SSUP + i] = g_support_g[i];
        }
        __syncthreads();
        gemm4p<true>(smem, wih, bih, bhh, t);
        elt4p(smem, smem + SXP, cst, t, row0, 0, out);
    } else if (bid < 48) {
        int cb = bid - 32;
        if (t < 160) {
            int j = t >> 5;
            int cp = cb * 32 + (t & 31);
            int colo = (cp >> 7) * 256 + (cp & 127);
            float acc = 0.0f;
            #pragma unroll 16
            for (int k = 0; k < 128; k++)
                acc += g_support_g[j * 128 + k] * whh[(size_t)(128 + k) * 1024 + colo];
            g_SW[j * 512 + cp] = acc;
        }
    }
    grid_bar_on(&g_bar2, bbase, 1, GRID2);

    if (bid < 32) {
        #pragma unroll
        for (int s = 1; s < 4; s++) {
            gemm4p<false>(smem, whh, nullptr, nullptr, t);
            elt4p(smem, smem + SP1, cst, t, row0, (s == 3) ? 1 : 0, out);
        }
    }
}

// ---------------- host ----------------
extern "C" void kernel_launch(void* const* d_in, const int* in_sizes, int n_in,
                              void* d_out, int out_size) {
    const int2*  ql     = (const int2*)d_in[0];
    const int2*  qr     = (const int2*)d_in[1];
    const int2*  sl     = (const int2*)d_in[2];
    const int2*  sr     = (const int2*)d_in[3];
    const float* qld    = (const float*)d_in[4];
    const float* qrd    = (const float*)d_in[5];
    const float* sld    = (const float*)d_in[6];
    const float* srd    = (const float*)d_in[7];
    const float* ent    = (const float*)d_in[8];
    const float* relm   = (const float*)d_in[9];
    const float* gcn_w  = (const float*)d_in[10];
    const float* gcn_wb = (const float*)d_in[11];
    const float* gcn_b  = (const float*)d_in[12];
    const float* se_w1  = (const float*)d_in[13];
    const float* se_b1  = (const float*)d_in[14];
    const float* se_w2  = (const float*)d_in[15];
    const float* se_b2  = (const float*)d_in[16];
    const float* ln_g   = (const float*)d_in[17];
    const float* ln_b   = (const float*)d_in[18];
    const float* wih    = (const float*)d_in[19];
    const float* whh    = (const float*)d_in[20];
    const float* bih    = (const float*)d_in[21];
    const float* bhh    = (const float*)d_in[22];
    float* out = (float*)d_out;

    k1_scatter_rescal<<<GRID1, NT>>>(ql, qr, sl, sr, ent, relm);
    k2_tail<<<GRID2, NT>>>(qld, qrd, sld, srd, gcn_w, gcn_wb, gcn_b,
                           se_w1, se_b1, se_w2, se_b2, ln_g, ln_b,
                           wih, whh, bih, bhh, out);
}

// round 17
// speedup vs baseline: 1.0684x; 1.0684x over previous
#include <cuda_runtime.h>
#include <math.h>
#include <stdint.h>

#define Dd 64
#define DM 128
#define DI 256
#define Bq 128
#define NN 200
#define FEW 5
#define NRELS 500
#define NPQ (Bq*NN)
#define NPS (FEW*NN)
#define NPTOT (2*NPQ + 2*NPS)   // 53200
#define CAP 512
#define SUBCAP 256
#define LN_EPS 0.001f
#define GRID1 296               // rescal: 2 blocks/SM
#define GRID2 148
#define NT 512
#define SCHUNK 360              // 148*360 >= 53200
#define NROWS (Bq + FEW)        // 133
#define SUMSZ (NROWS * 128)

// k2 stage-A smem layout
#define AMS   0
#define AX    128
#define APART 256
#define ASA   768
#define ASH   1024
#define ASR   1152
#define ASC   1216

// k2 stage-B/C smem layout — packed 512-col gates
#define SXP   0
#define SP1   2048
#define SP2   4096
#define SP3   6144
#define SHT   8192
#define SQ    8704
#define SSUP  9216
#define SLOG  9856
#define SATT  9888
#define SRED  9920
#define SMEMF 10240

// ---------------- device scratch ----------------
__device__ int   g_cnt[1024];                // [rel*2+sub]; zero-init; self-zeroed by rescal pops
__device__ int2  g_pairs[NRELS*CAP + 8];     // [rel*CAP + sub*SUBCAP + pos]
__device__ float g_sum[SUMSZ];               // natural layout [row][col]
__device__ float g_query_g[Bq*DM];
__device__ float g_support_g[FEW*DM];
__device__ float g_SW[FEW*512];
__device__ int   g_relctr;
__device__ unsigned long long g_bar2;        // k2 barrier counter, monotonic

__device__ __forceinline__ float sigmoidf_(float x) { return 1.0f / (1.0f + expf(-x)); }

#define FPACK2(d, f)      asm("mov.b64 %0, {%1, %1};" : "=l"(d) : "f"(f))
#define FMA2(acc, e, r)   asm("fma.rn.f32x2 %0, %1, %2, %3;" : "=l"(acc) : "l"(e), "l"(r), "l"(acc))
#define UNPACK2(lo, hi, v) asm("mov.b64 {%0, %1}, %2;" : "=f"(lo), "=f"(hi) : "l"(v))

__device__ __forceinline__ unsigned long long ctr_read(unsigned long long* p) {
    unsigned long long v;
    asm volatile("ld.global.acquire.gpu.u64 %0, [%1];" : "=l"(v) : "l"(p) : "memory");
    return v;
}
__device__ __forceinline__ void grid_bar_on(unsigned long long* p, unsigned long long base,
                                            int k, int n) {
    __syncthreads();
    if (threadIdx.x == 0) {
        __threadfence();
        atomicAdd(p, 1ULL);
        unsigned long long target = base + (unsigned long long)n * (unsigned long long)(k + 1);
        while (ctr_read(p) < target) {}
        __threadfence();
    }
    __syncthreads();
}

__device__ __forceinline__ int dest_base(int idx) {
    if (idx < 2*NPQ) {
        int half = (idx >= NPQ);
        int b = (idx - half * NPQ) / NN;
        return b * 128 + half * 64;
    } else {
        int i2 = idx - 2*NPQ;
        int half = (i2 >= NPS);
        int s = (i2 - half * NPS) / NN;
        return (Bq + s) * 128 + half * 64;
    }
}

// ================= KERNEL 0: zero + sub-binned scatter =================
__global__ __launch_bounds__(NT, 1) void k0_scatter(
        const int2* __restrict__ ql, const int2* __restrict__ qr,
        const int2* __restrict__ sl, const int2* __restrict__ sr) {
    int t = threadIdx.x, bid = blockIdx.x;
    if (bid == 0 && t == 0) g_relctr = 0;
    for (int i = bid * NT + t; i < SUMSZ; i += GRID2 * NT) g_sum[i] = 0.0f;
    int lo = bid * SCHUNK, hi = min(lo + SCHUNK, NPTOT);
    for (int idx = lo + t; idx < hi; idx += NT) {
        int2 c;
        if (idx < NPQ)                 c = ql[idx];
        else if (idx < 2*NPQ)          c = qr[idx - NPQ];
        else if (idx < 2*NPQ + NPS)    c = sl[idx - 2*NPQ];
        else                           c = sr[idx - 2*NPQ - NPS];
        int sub = idx & 1;
        int pos = atomicAdd(&g_cnt[c.x * 2 + sub], 1);
        if (pos < SUBCAP) g_pairs[c.x * CAP + sub * SUBCAP + pos] = make_int2(idx, c.y);
    }
}

// ================= KERNEL 1: binned RESCAL (2-segment bins) =================
__global__ __launch_bounds__(NT, 2) void k1_rescal(
        const float* __restrict__ ent_emb, const float* __restrict__ rel_mat) {
    __shared__ __align__(16) float sR[4352];        // pitch-68 R tile
    __shared__ __align__(16) float sE01[16][128];
    __shared__ __align__(16) float sE23[16][128];
    __shared__ int s_r;
    __shared__ int s_c0, s_c1;
    int t = threadIdx.x;
    int w = t >> 5, lane = t & 31;
    float* e01 = &sE01[w][0];
    float* e23 = &sE23[w][0];
    for (;;) {
        if (t == 0) {
            int r = atomicAdd(&g_relctr, 1);
            s_r = r;
            if (r < NRELS) {
                s_c0 = g_cnt[2*r];     g_cnt[2*r] = 0;
                s_c1 = g_cnt[2*r + 1]; g_cnt[2*r + 1] = 0;
            }
        }
        __syncthreads();
        int r = s_r;
        if (r >= NRELS) break;
        int c0 = min(s_c0, SUBCAP), c1 = min(s_c1, SUBCAP);
        if (c0 + c1 > 0) {
            const float* R = rel_mat + (size_t)r * 4096;
            for (int i = t; i < 4096; i += NT) sR[(i >> 6) * 68 + (i & 63)] = R[i];
            __syncthreads();
            #pragma unroll
            for (int seg = 0; seg < 2; seg++) {
                int cs = seg ? c1 : c0;
                const int2* bin = g_pairs + r * CAP + seg * SUBCAP;
                for (int base = w * 4; base < cs; base += 64) {
                    int np = min(4, cs - base);
                    int2 pr[4];
                    float2 ev[4];
                    #pragma unroll
                    for (int p = 0; p < 4; p++) pr[p] = bin[base + p];
                    #pragma unroll
                    for (int p = 0; p < 4; p++)
                        ev[p] = ((const float2*)(ent_emb + (size_t)pr[p].y * 64))[lane];
                    #pragma unroll
                    for (int p = 0; p < 4; p++) {
                        float* dstE = (p < 2) ? e01 : e23;
                        int pp = p & 1;
                        dstE[4*lane + pp]     = ev[p].x;
                        dstE[4*lane + 2 + pp] = ev[p].y;
                    }
                    __syncwarp();
                    unsigned long long aA01=0, aA23=0, aB01=0, aB23=0;
                    #pragma unroll
                    for (int j4 = 0; j4 < 64; j4 += 4) {
                        float4 rA = *(const float4*)&sR[lane * 68 + j4];
                        float4 rB = *(const float4*)&sR[(lane + 32) * 68 + j4];
                        ulonglong2 E01a = *(const ulonglong2*)(e01 + j4*2);
                        ulonglong2 E01b = *(const ulonglong2*)(e01 + j4*2 + 4);
                        ulonglong2 E23a = *(const ulonglong2*)(e23 + j4*2);
                        ulonglong2 E23b = *(const ulonglong2*)(e23 + j4*2 + 4);
                        unsigned long long dA, dB;
                        FPACK2(dA, rA.x); FPACK2(dB, rB.x);
                        FMA2(aA01, E01a.x, dA); FMA2(aA23, E23a.x, dA);
                        FMA2(aB01, E01a.x, dB); FMA2(aB23, E23a.x, dB);
                        FPACK2(dA, rA.y); FPACK2(dB, rB.y);
                        FMA2(aA01, E01a.y, dA); FMA2(aA23, E23a.y, dA);
                        FMA2(aB01, E01a.y, dB); FMA2(aB23, E23a.y, dB);
                        FPACK2(dA, rA.z); FPACK2(dB, rB.z);
                        FMA2(aA01, E01b.x, dA); FMA2(aA23, E23b.x, dA);
                        FMA2(aB01, E01b.x, dB); FMA2(aB23, E23b.x, dB);
                        FPACK2(dA, rA.w); FPACK2(dB, rB.w);
                        FMA2(aA01, E01b.y, dA); FMA2(aA23, E23b.y, dA);
                        FMA2(aB01, E01b.y, dB); FMA2(aB23, E23b.y, dB);
                    }
                    float accA[4], accB[4];
                    UNPACK2(accA[0], accA[1], aA01); UNPACK2(accA[2], accA[3], aA23);
                    UNPACK2(accB[0], accB[1], aB01); UNPACK2(accB[2], accB[3], aB23);
                    #pragma unroll
                    for (int p = 0; p < 4; p++) {
                        if (p < np) {
                            int db = dest_base(pr[p].x);
                            asm volatile("red.global.add.f32 [%0], %1;"
                                :: "l"(&g_sum[db + lane]), "f"(accA[p]) : "memory");
                            asm volatile("red.global.add.f32 [%0], %1;"
                                :: "l"(&g_sum[db + lane + 32]), "f"(accB[p]) : "memory");
                        }
                    }
                    __syncwarp();
                }
            }
        }
        __syncthreads();   // protect sR / s_r / s_c reuse
    }
}

// ---------------- packed 4-row GEMM: (4x128) @ (128 x packed512), 4-way K-split ----------------
template<bool XPROJ>
__device__ __forceinline__ void gemm4p(float* sm, const float* __restrict__ Bmat,
        const float* __restrict__ bih, const float* __restrict__ bhh, int t) {
    int kh = t >> 7, u = t & 127;
    int c4p = u * 4;
    int gate = c4p >> 7;
    int colo = gate * 256 + (c4p & 127);
    const float* Bp = Bmat + (size_t)(kh * 32) * 1024 + colo;
    const float* Ap = sm + SHT + kh * 32 * 4;
    unsigned long long acc[8];
    #pragma unroll
    for (int i = 0; i < 8; i++) acc[i] = 0ULL;
    #pragma unroll 8
    for (int k = 0; k < 32; k++) {
        float4 a4 = *(const float4*)(Ap + k * 4);
        ulonglong2 bv = *(const ulonglong2*)(Bp + (size_t)k * 1024);
        unsigned long long ar;
        FPACK2(ar, a4.x); FMA2(acc[0], bv.x, ar); FMA2(acc[1], bv.y, ar);
        FPACK2(ar, a4.y); FMA2(acc[2], bv.x, ar); FMA2(acc[3], bv.y, ar);
        FPACK2(ar, a4.z); FMA2(acc[4], bv.x, ar); FMA2(acc[5], bv.y, ar);
        FPACK2(ar, a4.w); FMA2(acc[6], bv.x, ar); FMA2(acc[7], bv.y, ar);
    }
    if (kh) {
        float* pdst = sm + SP1 + (kh - 1) * 2048;
        #pragma unroll
        for (int r = 0; r < 4; r++) {
            float o0, o1, o2, o3;
            UNPACK2(o0, o1, acc[r*2]); UNPACK2(o2, o3, acc[r*2+1]);
            *(float4*)&pdst[r * 512 + c4p] = make_float4(o0, o1, o2, o3);
        }
    }
    __syncthreads();
    if (kh == 0) {
        float4 sw[FEW];
        float4 bb;
        if (XPROJ) {
            bb = make_float4(bih[colo]+bhh[colo], bih[colo+1]+bhh[colo+1],
                             bih[colo+2]+bhh[colo+2], bih[colo+3]+bhh[colo+3]);
        } else {
            #pragma unroll
            for (int j = 0; j < FEW; j++) sw[j] = *(const float4*)&g_SW[j * 512 + c4p];
        }
        #pragma unroll
        for (int r = 0; r < 4; r++) {
            float o0, o1, o2, o3;
            UNPACK2(o0, o1, acc[r*2]); UNPACK2(o2, o3, acc[r*2+1]);
            float4 p1 = *(const float4*)&sm[SP1 + r * 512 + c4p];
            float4 p2 = *(const float4*)&sm[SP2 + r * 512 + c4p];
            float4 p3 = *(const float4*)&sm[SP3 + r * 512 + c4p];
            o0 += p1.x + p2.x + p3.x; o1 += p1.y + p2.y + p3.y;
            o2 += p1.z + p2.z + p3.z; o3 += p1.w + p2.w + p3.w;
            if (XPROJ) {
                o0 += bb.x; o1 += bb.y; o2 += bb.z; o3 += bb.w;
                *(float4*)&sm[SXP + r * 512 + c4p] = make_float4(o0, o1, o2, o3);
            } else {
                float4 xv = *(const float4*)&sm[SXP + r * 512 + c4p];
                o0 += xv.x; o1 += xv.y; o2 += xv.z; o3 += xv.w;
                #pragma unroll
                for (int j = 0; j < FEW; j++) {
                    float aj = sm[SATT + r * 8 + j];
                    o0 += aj * sw[j].x; o1 += aj * sw[j].y;
                    o2 += aj * sw[j].z; o3 += aj * sw[j].w;
                }
                *(float4*)&sm[SP1 + r * 512 + c4p] = make_float4(o0, o1, o2, o3);
            }
        }
    }
    __syncthreads();
}

// ---------------- LSTM elementwise + attention, 2-sync version ----------------
__device__ __forceinline__ void elt4p(float* sm, const float* __restrict__ gp_base,
                                      float& c, int t, int row0, int last, float* __restrict__ out) {
    int r = t >> 7, u = t & 127;
    const float* gp = gp_base + r * 512;
    float gi = gp[u], gf = gp[128 + u], gg = gp[256 + u], go = gp[384 + u];
    c = sigmoidf_(gf) * c + sigmoidf_(gi) * tanhf(gg);
    float h = sm[SQ + r * 128 + u] + sigmoidf_(go) * tanhf(c);
    sm[SHT + u * 4 + r] = h;
    int lane = t & 31, wid = t >> 5;
    float p[FEW];
    #pragma unroll
    for (int j = 0; j < FEW; j++) p[j] = h * sm[SSUP + j * 128 + u];
    #pragma unroll
    for (int j = 0; j < FEW; j++)
        for (int o = 16; o; o >>= 1) p[j] += __shfl_down_sync(0xffffffff, p[j], o);
    if (lane == 0) {
        #pragma unroll
        for (int j = 0; j < FEW; j++) sm[SRED + wid * 5 + j] = p[j];
    }
    __syncthreads();
    if (t < 32) {
        int rr = t >> 3, j = t & 7;
        if (j < FEW) {
            int w0 = rr * 4;
            sm[SLOG + rr * 8 + j] = sm[SRED + w0*5 + j] + sm[SRED + (w0+1)*5 + j]
                                  + sm[SRED + (w0+2)*5 + j] + sm[SRED + (w0+3)*5 + j];
        }
    }
    __syncthreads();
    if (last) {
        if (t < 4) {
            #pragma unroll
            for (int j = 0; j < FEW; j++) out[(row0 + t) * FEW + j] = sm[SLOG + t * 8 + j];
        }
        return;
    }
    if (t < 4) {
        float mx = sm[SLOG + t * 8];
        #pragma unroll
        for (int j = 1; j < FEW; j++) mx = fmaxf(mx, sm[SLOG + t * 8 + j]);
        float s = 0.0f, e[FEW];
        #pragma unroll
        for (int j = 0; j < FEW; j++) { e[j] = expf(sm[SLOG + t * 8 + j] - mx); s += e[j]; }
        #pragma unroll
        for (int j = 0; j < FEW; j++) sm[SATT + t * 8 + j] = e[j] / s;
    }
    __syncthreads();
}

// ================= KERNEL 2: gcn+supp + LSTM tail =================
__global__ __launch_bounds__(NT, 1) void k2_tail(
        const float* __restrict__ qld, const float* __restrict__ qrd,
        const float* __restrict__ sld, const float* __restrict__ srd,
        const float* __restrict__ gcn_w, const float* __restrict__ gcn_wb, const float* __restrict__ gcn_b,
        const float* __restrict__ w1, const float* __restrict__ b1,
        const float* __restrict__ w2, const float* __restrict__ b2,
        const float* __restrict__ lg, const float* __restrict__ lb,
        const float* __restrict__ wih, const float* __restrict__ whh,
        const float* __restrict__ bih, const float* __restrict__ bhh,
        float* __restrict__ out) {
    __shared__ __align__(16) float smem[SMEMF];
    __shared__ unsigned long long s_base;
    int t = threadIdx.x, bid = blockIdx.x;
    if (t == 0) s_base = (ctr_read(&g_bar2) / (2ULL * GRID2)) * (2ULL * GRID2);
    __syncthreads();
    unsigned long long bbase = s_base;

    if (bid < NROWS) {
        if (t < 128) smem[AMS + t] = g_sum[bid * 128 + t];
        __syncthreads();
        {
            int o = t & 127, ks = t >> 7;
            int hh = o >> 6, col = o & 63;
            float acc = 0.0f;
            #pragma unroll
            for (int i = 0; i < 16; i++) {
                int k = ks * 16 + i;
                acc += smem[AMS + hh * 64 + k] * gcn_w[k * 64 + col];
            }
            smem[APART + ks * 128 + o] = acc;
        }
        __syncthreads();
        float degL = (bid < Bq) ? qld[bid] : sld[bid - Bq];
        float degR = (bid < Bq) ? qrd[bid] : srd[bid - Bq];
        if (t < 128) {
            float acc = smem[APART + t] + smem[APART + 128 + t]
                      + smem[APART + 256 + t] + smem[APART + 384 + t];
            acc += (float)NN * (gcn_wb[t & 63] + gcn_b[t & 63]);
            smem[AX + t] = tanhf(acc / ((t >> 6) ? degR : degL));
        }
        __syncthreads();
        {   // GEMV1: 2-way k-split, 4 accumulators
            int half = t >> 8, o = t & 255;
            float a0 = 0.f, a1 = 0.f, a2 = 0.f, a3 = 0.f;
            const float* xk = smem + AX + half * 64;
            const float* wk = w1 + (size_t)(half * 64) * DI + o;
            #pragma unroll
            for (int i = 0; i < 64; i += 4) {
                a0 += xk[i]   * wk[(size_t)i * DI];
                a1 += xk[i+1] * wk[(size_t)(i+1) * DI];
                a2 += xk[i+2] * wk[(size_t)(i+2) * DI];
                a3 += xk[i+3] * wk[(size_t)(i+3) * DI];
            }
            smem[APART + half * 256 + o] = (a0 + a1) + (a2 + a3);
        }
        __syncthreads();
        if (t < DI) smem[ASA + t] = fmaxf(smem[APART + t] + smem[APART + 256 + t] + b1[t], 0.0f);
        __syncthreads();
        {   // GEMV2: 4-way k-split, 4 accumulators
            int ks = t >> 7, o = t & 127;
            float a0 = 0.f, a1 = 0.f, a2 = 0.f, a3 = 0.f;
            const float* xk = smem + ASA + ks * 64;
            const float* wk = w2 + (size_t)(ks * 64) * DM + o;
            #pragma unroll
            for (int i = 0; i < 64; i += 4) {
                a0 += xk[i]   * wk[(size_t)i * DM];
                a1 += xk[i+1] * wk[(size_t)(i+1) * DM];
                a2 += xk[i+2] * wk[(size_t)(i+2) * DM];
                a3 += xk[i+3] * wk[(size_t)(i+3) * DM];
            }
            smem[APART + ks * 128 + o] = (a0 + a1) + (a2 + a3);
        }
        __syncthreads();
        if (t < DM) {
            smem[ASH + t] = smem[APART + t] + smem[APART + 128 + t] + smem[APART + 256 + t]
                          + smem[APART + 384 + t] + b2[t] + smem[AX + t];
        }
        __syncthreads();
        if (t < 64) smem[ASR + t] = smem[ASH + t] + smem[ASH + t + 64];
        __syncthreads();
        if (t < 32) {
            float v = smem[ASR + t] + smem[ASR + t + 32];
            for (int o = 16; o; o >>= 1) v += __shfl_down_sync(0xffffffff, v, o);
            if (t == 0) smem[ASC] = v / (float)DM;
        }
        __syncthreads();
        float mu = smem[ASC];
        if (t < 64) {
            float d0 = smem[ASH + t] - mu, d1 = smem[ASH + t + 64] - mu;
            smem[ASR + t] = d0 * d0 + d1 * d1;
        }
        __syncthreads();
        if (t < 32) {
            float v = smem[ASR + t] + smem[ASR + t + 32];
            for (int o = 16; o; o >>= 1) v += __shfl_down_sync(0xffffffff, v, o);
            if (t == 0) smem[ASC + 1] = sqrtf(v / (float)(DM - 1));
        }
        __syncthreads();
        if (t < DM) {
            float* y = (bid < Bq) ? (g_query_g + bid * DM) : (g_support_g + (bid - Bq) * DM);
            y[t] = (smem[ASH + t] - mu) / (smem[ASC + 1] + LN_EPS) * lg[t] + lb[t];
        }
    }
    grid_bar_on(&g_bar2, bbase, 0, GRID2);

    int row0 = bid * 4;
    float cst = 0.0f;
    if (bid < 32) {
        {
            int r = t >> 7, k = t & 127;
            float v = g_query_g[(size_t)(row0 + r) * 128 + k];
            smem[SHT + k * 4 + r] = v;
            smem[SQ + r * 128 + k] = v;
            for (int i = t; i < FEW * 128; i += NT) smem[SSUP + i] = g_support_g[i];
        }
        __syncthreads();
        gemm4p<true>(smem, wih, bih, bhh, t);
        elt4p(smem, smem + SXP, cst, t, row0, 0, out);
    } else if (bid < 48) {
        int cb = bid - 32;
        if (t < 160) {
            int j = t >> 5;
            int cp = cb * 32 + (t & 31);
            int colo = (cp >> 7) * 256 + (cp & 127);
            float acc = 0.0f;
            #pragma unroll 16
            for (int k = 0; k < 128; k++)
                acc += g_support_g[j * 128 + k] * whh[(size_t)(128 + k) * 1024 + colo];
            g_SW[j * 512 + cp] = acc;
        }
    }
    grid_bar_on(&g_bar2, bbase, 1, GRID2);

    if (bid < 32) {
        #pragma unroll
        for (int s = 1; s < 4; s++) {
            gemm4p<false>(smem, whh, nullptr, nullptr, t);
            elt4p(smem, smem + SP1, cst, t, row0, (s == 3) ? 1 : 0, out);
        }
    }
}

// ---------------- host ----------------
extern "C" void kernel_launch(void* const* d_in, const int* in_sizes, int n_in,
                              void* d_out, int out_size) {
    const int2*  ql     = (const int2*)d_in[0];
    const int2*  qr     = (const int2*)d_in[1];
    const int2*  sl     = (const int2*)d_in[2];
    const int2*  sr     = (const int2*)d_in[3];
    const float* qld    = (const float*)d_in[4];
    const float* qrd    = (const float*)d_in[5];
    const float* sld    = (const float*)d_in[6];
    const float* srd    = (const float*)d_in[7];
    const float* ent    = (const float*)d_in[8];
    const float* relm   = (const float*)d_in[9];
    const float* gcn_w  = (const float*)d_in[10];
    const float* gcn_wb = (const float*)d_in[11];
    const float* gcn_b  = (const float*)d_in[12];
    const float* se_w1  = (const float*)d_in[13];
    const float* se_b1  = (const float*)d_in[14];
    const float* se_w2  = (const float*)d_in[15];
    const float* se_b2  = (const float*)d_in[16];
    const float* ln_g   = (const float*)d_in[17];
    const float* ln_b   = (const float*)d_in[18];
    const float* wih    = (const float*)d_in[19];
    const float* whh    = (const float*)d_in[20];
    const float* bih    = (const float*)d_in[21];
    const float* bhh    = (const float*)d_in[22];
    float* out = (float*)d_out;

    k0_scatter<<<GRID2, NT>>>(ql, qr, sl, sr);
    k1_rescal<<<GRID1, NT>>>(ent, relm);
    k2_tail<<<GRID2, NT>>>(qld, qrd, sld, srd, gcn_w, gcn_wb, gcn_b,
                           se_w1, se_b1, se_w2, se_b2, ln_g, ln_b,
                           wih, whh, bih, bhh, out);
}